// round 15
// baseline (speedup 1.0000x reference)
#include <cuda_runtime.h>
#include <cstdint>

// Problem constants (fixed for rotary_13872744366393):
//   x: (4, 8192, 1024) f32, matrix: (64,64), thetas: (32), tscale: (1),
//   invf: (32), pairs: (32,2) int32. out: (4, 8192, 1024) f32.
#define HEADS 16
#define D     64
#define ROTN  32
#define SEQ   8192

// Pre-built bf16 B fragments for mma.m16n8k16:
//   g_Bfrag[(kt*8 + j)*32 + lane] = {bhi0, bhi1, blo0, blo1} (packed bf16x2)
//   bhi0 = (Mhi[k0][n], Mhi[k0+1][n]), bhi1 = (Mhi[k0+8][n], Mhi[k0+9][n])
// with k0 = kt*16 + 2*tig, n = 8*j + g  (g = lane>>2, tig = lane&3).
__device__ uint4 g_Bfrag[4 * 8 * 32];     // 16 KB

// pack two fp32 into bf16x2 (rn): low half = lo, high half = hi
__device__ __forceinline__ uint32_t pack_bf16x2(float lo, float hi) {
    uint32_t r;
    asm("cvt.rn.bf16x2.f32 %0, %1, %2;" : "=r"(r) : "f"(hi), "f"(lo));
    return r;
}
// bf16 halves of a packed u32 back to fp32 (pure bit placement)
__device__ __forceinline__ float bf_lo_f32(uint32_t p) {
    return __uint_as_float(p << 16);
}
__device__ __forceinline__ float bf_hi_f32(uint32_t p) {
    return __uint_as_float(p & 0xFFFF0000u);
}

__device__ __forceinline__ uint32_t smem_u32(const void* p) {
    uint32_t a;
    asm("{ .reg .u64 t; cvta.to.shared.u64 t, %1; cvt.u32.u64 %0, t; }"
        : "=r"(a) : "l"(p));
    return a;
}

// m16n8k16 bf16 MMA, D = A@B + D (fp32 accum)
#define MMA_BF16(d, a, b)                                                     \
    asm volatile("mma.sync.aligned.m16n8k16.row.col.f32.bf16.bf16.f32 "       \
                 "{%0,%1,%2,%3}, {%4,%5,%6,%7}, {%8,%9}, {%0,%1,%2,%3};"      \
                 : "+f"((d)[0]), "+f"((d)[1]), "+f"((d)[2]), "+f"((d)[3])     \
                 : "r"((a)[0]), "r"((a)[1]), "r"((a)[2]), "r"((a)[3]),        \
                   "r"((b)[0]), "r"((b)[1]))

// ldmatrix x4: loads a full m16k16 b16 A fragment (4 regs) in one instruction
#define LDMATRIX_X4(r, addr)                                                  \
    asm volatile("ldmatrix.sync.aligned.m8n8.x4.shared.b16 "                  \
                 "{%0,%1,%2,%3}, [%4];"                                       \
                 : "=r"((r)[0]), "=r"((r)[1]), "=r"((r)[2]), "=r"((r)[3])     \
                 : "r"(addr))

// ---------------------------------------------------------------------------
// Kernel 1: build M = G_comb @ matrix; emit packed-bf16 hi/lo B FRAGMENTS.
// G_comb = I @ G_0 @ ... @ G_31 ; right-multiplying by G_q updates COLUMNS:
//   col_i' = col_i*c + col_j*s ;  col_j' = -col_i*s + col_j*c
// Degenerate i==j (JAX .at sequence leaves G[i,i] = sin): col_i' = col_i*s
// ---------------------------------------------------------------------------
__global__ void build_M_kernel(const float* __restrict__ matrix,
                               const float* __restrict__ thetas,
                               const float* __restrict__ tscale,
                               const int*   __restrict__ pairs) {
    __shared__ float Gs[64][65];
    __shared__ float Mat[64][64];
    __shared__ float Msh[64][64];
    __shared__ float ssin[ROTN], scos[ROTN];
    __shared__ int   sij[ROTN][2];
    const int tid = threadIdx.x;   // 256 threads

    for (int i = tid; i < 64 * 64; i += 256)
        Mat[i >> 6][i & 63] = matrix[i];

    if (tid < ROTN) {                      // sincos once, not per-row
        const float th = thetas[tid] * tscale[0];
        float s, c;
        sincosf(th, &s, &c);
        ssin[tid] = s;
        scos[tid] = c;
        sij[tid][0] = pairs[2 * tid];
        sij[tid][1] = pairs[2 * tid + 1];
    }
    if (tid < 64) {
        #pragma unroll
        for (int k = 0; k < 64; k++) Gs[tid][k] = (tid == k) ? 1.0f : 0.0f;
    }
    __syncthreads();

    if (tid < 64) {
        for (int q = 0; q < ROTN; q++) {
            const int   i = sij[q][0];
            const int   j = sij[q][1];
            const float s = ssin[q];
            const float c = scos[q];
            const float ai = Gs[tid][i];
            const float aj = Gs[tid][j];
            if (i != j) {
                Gs[tid][i] = ai * c + aj * s;
                Gs[tid][j] = -ai * s + aj * c;
            } else {
                Gs[tid][i] = ai * s;
            }
        }
    }
    __syncthreads();

    {
        const int r  = tid >> 2;
        const int qq = tid & 3;
        float gr[64];
        #pragma unroll
        for (int k = 0; k < 64; k++) gr[k] = Gs[r][k];
        #pragma unroll
        for (int n0 = 0; n0 < 16; n0++) {
            const int n = qq * 16 + n0;
            float acc = 0.0f;
            #pragma unroll
            for (int k = 0; k < 64; k++) acc = fmaf(gr[k], Mat[k][n], acc);
            Msh[r][n] = acc;
        }
    }
    __syncthreads();

    // emit fragment-ordered B: hi = bf16(M), lo = bf16(M - hi)
    for (int idx = tid; idx < 4 * 8 * 32; idx += 256) {
        const int frag = idx >> 5;           // kt*8 + j
        const int lane = idx & 31;
        const int kt = frag >> 3, j = frag & 7;
        const int g = lane >> 2, tg = lane & 3;
        const int k0 = kt * 16 + 2 * tg;
        const int n  = 8 * j + g;
        uint4 o;
        {
            const float m0 = Msh[k0][n],     m1 = Msh[k0 + 1][n];
            o.x = pack_bf16x2(m0, m1);
            o.z = pack_bf16x2(m0 - bf_lo_f32(o.x), m1 - bf_hi_f32(o.x));
        }
        {
            const float m0 = Msh[k0 + 8][n], m1 = Msh[k0 + 9][n];
            o.y = pack_bf16x2(m0, m1);
            o.w = pack_bf16x2(m0 - bf_lo_f32(o.y), m1 - bf_hi_f32(o.y));
        }
        g_Bfrag[idx] = o;
    }
}

// ---------------------------------------------------------------------------
// Kernel 2: bf16 m16n8k16 mma.sync GEMM (3-term compensated) + RoPE epilogue.
// CTA = 128 threads (4 warps), tile = 128 rows x 64 cols, K = 64 (4 kt).
// Warp w: rows [w*32, w*32+32) = two m16 tiles; 8 n8-tiles cover 64 cols.
// A stored as NATURAL bf16 rows (hi and lo arrays), 144 B row stride
// (144 mod 128 = 16 -> ldmatrix's 8-row phases hit 8 distinct bank sets).
// A fragments loaded with ldmatrix.x4 (one instr = full m16k16 fragment),
// which also kills the R14 k-pair permutation and its scattered STS.
// B fragments pre-built: one LDS.128 per (kt,j) carries hi+lo.
// Double-buffered across kt under __launch_bounds__(128, 2).
// Epilogue: RoPE in regs -> conflict-free STS.32 scatter -> LDS.128+STG.128.
// ---------------------------------------------------------------------------
#define A_ROW_B  144                               // bytes per bf16 row
#define SM_AH    0                                 // 128*144 = 18432 B
#define SM_AL    18432                             // 18432 B
#define SM_BF    36864                             // 16384 B
#define SM_SC    53248                             // 2048 B
#define SMEM_DYN 55296
#define O_STRIDE 68                                // epilogue scatter stride

__global__ __launch_bounds__(128, 2)
void rotary_mma(const float* __restrict__ x,
                const float* __restrict__ invf,
                float* __restrict__ out) {
    extern __shared__ __align__(16) char dsm[];
    uint4*  Bfs = (uint4*)(dsm + SM_BF);
    float2* sc  = (float2*)(dsm + SM_SC);

    const int tid  = threadIdx.x;
    const int w    = tid >> 5;
    const int lane = tid & 31;
    const int g    = lane >> 2;     // groupID 0..7
    const int tig  = lane & 3;      // threadID_in_group 0..3

    // ---- stage A: fp32 -> packed bf16x2 hi/lo, NATURAL row layout ----
    {
        const float4* xg = (const float4*)(x + (size_t)blockIdx.x * 128 * 64);
        #pragma unroll
        for (int i = 0; i < 16; i++) {
            const int idx = i * 128 + tid;        // 16B chunk id, 2048 total
            const int row = idx >> 4;
            const int kq  = idx & 15;             // 4-float chunk within row
            const float4 v = xg[idx];
            const uint32_t h0 = pack_bf16x2(v.x, v.y);
            const uint32_t h1 = pack_bf16x2(v.z, v.w);
            const uint32_t l0 =
                pack_bf16x2(v.x - bf_lo_f32(h0), v.y - bf_hi_f32(h0));
            const uint32_t l1 =
                pack_bf16x2(v.z - bf_lo_f32(h1), v.w - bf_hi_f32(h1));
            const int off = row * A_ROW_B + kq * 8;
            *(uint2*)(dsm + SM_AH + off) = make_uint2(h0, h1);
            *(uint2*)(dsm + SM_AL + off) = make_uint2(l0, l1);
        }
    }

    // ---- stage B fragments: 1024 uint4, 8 per thread ----
    {
        #pragma unroll
        for (int i = 0; i < 8; i++) {
            const int idx = tid + 128 * i;
            Bfs[idx] = g_Bfrag[idx];
        }
    }

    // ---- sincos table: 8 tokens x 32 freqs ----
    {
        #pragma unroll
        for (int e = 0; e < 2; e++) {
            const int idx = tid * 2 + e;          // 256 entries
            const int t = idx >> 5, m = idx & 31;
            const int pos = (blockIdx.x * 8 + t) & (SEQ - 1);
            float sn, cs;
            sincosf((float)pos * invf[m], &sn, &cs);
            sc[idx] = make_float2(sn, cs);
        }
    }
    __syncthreads();

    // ---- mainloop: 4 kt steps, double-buffered A (ldmatrix) + B frags ----
    float acc[2][8][4];
    #pragma unroll
    for (int mt = 0; mt < 2; mt++)
        #pragma unroll
        for (int j = 0; j < 8; j++)
            #pragma unroll
            for (int q = 0; q < 4; q++) acc[mt][j][q] = 0.0f;

    // ldmatrix per-lane address: row = w*32 + mt*16 + (lane&15),
    // k-byte = kt*32 + (lane & 16).
    const uint32_t smb = smem_u32(dsm);
    const uint32_t ahb = smb + SM_AH
                       + (w * 32 + (lane & 15)) * A_ROW_B + (lane & 16);
    const uint32_t alb = ahb + (SM_AL - SM_AH);
    const uint4* Bbase = Bfs + lane;

    uint32_t fh[2][2][4], fl[2][2][4];
    uint4 pb[2][8];

    // prefetch kt = 0
    #pragma unroll
    for (int mt = 0; mt < 2; mt++) {
        LDMATRIX_X4(fh[0][mt], ahb + mt * 16 * A_ROW_B);
        LDMATRIX_X4(fl[0][mt], alb + mt * 16 * A_ROW_B);
    }
    #pragma unroll
    for (int j = 0; j < 8; j++) pb[0][j] = Bbase[j * 32];

    #pragma unroll
    for (int kt = 0; kt < 4; kt++) {
        const int cur = kt & 1, nxt = cur ^ 1;
        if (kt < 3) {
            #pragma unroll
            for (int mt = 0; mt < 2; mt++) {
                LDMATRIX_X4(fh[nxt][mt],
                            ahb + mt * 16 * A_ROW_B + (kt + 1) * 32);
                LDMATRIX_X4(fl[nxt][mt],
                            alb + mt * 16 * A_ROW_B + (kt + 1) * 32);
            }
            #pragma unroll
            for (int j = 0; j < 8; j++)
                pb[nxt][j] = Bbase[((kt + 1) * 8 + j) * 32];
        }

        #pragma unroll
        for (int j = 0; j < 8; j++) {
            const uint4 bf = pb[cur][j];
            uint32_t bh[2] = {bf.x, bf.y};
            uint32_t bl[2] = {bf.z, bf.w};
            #pragma unroll
            for (int mt = 0; mt < 2; mt++) {
                MMA_BF16(acc[mt][j], fh[cur][mt], bh);   // xh @ Mh
                MMA_BF16(acc[mt][j], fl[cur][mt], bh);   // xl @ Mh
                MMA_BF16(acc[mt][j], fh[cur][mt], bl);   // xh @ Ml
            }
        }
    }

    // ---- epilogue: RoPE + *32 in regs, STS.32 scatter (conflict-free),
    //      then coalesced LDS.128 -> STG.128 ----
    __syncthreads();                                     // A/B reads done
    float* Osm = (float*)dsm;                            // reuse as scratch
    #pragma unroll
    for (int mt = 0; mt < 2; mt++) {
        const int tok = 2 * w + mt;
        const int r0 = w * 32 + mt * 16 + g;
        #pragma unroll
        for (int j = 0; j < 8; j++) {
            const int m = 4 * j + tig;
            const float2 scm = sc[tok * 32 + m];         // (sin, cos)
            const float* a = acc[mt][j];
            Osm[r0 * O_STRIDE + m]            = (a[0] * scm.y - a[1] * scm.x) * 32.0f;
            Osm[r0 * O_STRIDE + m + 32]       = (a[0] * scm.x + a[1] * scm.y) * 32.0f;
            Osm[(r0 + 8) * O_STRIDE + m]      = (a[2] * scm.y - a[3] * scm.x) * 32.0f;
            Osm[(r0 + 8) * O_STRIDE + m + 32] = (a[2] * scm.x + a[3] * scm.y) * 32.0f;
        }
    }
    __syncthreads();

    {
        float4* og = (float4*)(out + (size_t)blockIdx.x * 128 * 64);
        #pragma unroll
        for (int i = 0; i < 16; i++) {
            const int idx = i * 128 + tid;        // 16B chunk id, 2048 total
            const int row = idx >> 4;
            const int kq  = idx & 15;
            og[idx] = *(const float4*)(Osm + row * O_STRIDE + kq * 4);
        }
    }
}

// ---------------------------------------------------------------------------
extern "C" void kernel_launch(void* const* d_in, const int* in_sizes, int n_in,
                              void* d_out, int out_size) {
    const float* x      = (const float*)d_in[0];
    const float* matrix = (const float*)d_in[1];
    const float* thetas = (const float*)d_in[2];
    const float* tscale = (const float*)d_in[3];
    const float* invf   = (const float*)d_in[4];
    const int*   pairs  = (const int*)d_in[5];
    float* out = (float*)d_out;

    static bool attr_set = false;
    if (!attr_set) {
        cudaFuncSetAttribute(rotary_mma,
                             cudaFuncAttributeMaxDynamicSharedMemorySize,
                             SMEM_DYN);
        attr_set = true;
    }

    const int nrows  = in_sizes[0] / D;      // 524288
    const int blocks = nrows / 128;          // 4096

    build_M_kernel<<<1, 256>>>(matrix, thetas, tscale, pairs);
    rotary_mma<<<blocks, 128, SMEM_DYN>>>(x, invf, out);
}

// round 16
// speedup vs baseline: 1.1341x; 1.1341x over previous
#include <cuda_runtime.h>
#include <cstdint>

// Problem constants (fixed for rotary_13872744366393):
//   x: (4, 8192, 1024) f32, matrix: (64,64), thetas: (32), tscale: (1),
//   invf: (32), pairs: (32,2) int32. out: (4, 8192, 1024) f32.
#define HEADS 16
#define D     64
#define ROTN  32
#define SEQ   8192

// Pre-built bf16 B fragments for mma.m16n8k16:
//   g_Bfrag[(kt*8 + j)*32 + lane] = {bhi0, bhi1, blo0, blo1} (packed bf16x2)
//   bhi0 = (Mhi[k0][n], Mhi[k0+1][n]), bhi1 = (Mhi[k0+8][n], Mhi[k0+9][n])
// with k0 = kt*16 + 2*tig, n = 8*j + g  (g = lane>>2, tig = lane&3).
__device__ uint4 g_Bfrag[4 * 8 * 32];     // 16 KB

// pack two fp32 into bf16x2 (rn): low half = lo, high half = hi
__device__ __forceinline__ uint32_t pack_bf16x2(float lo, float hi) {
    uint32_t r;
    asm("cvt.rn.bf16x2.f32 %0, %1, %2;" : "=r"(r) : "f"(hi), "f"(lo));
    return r;
}
// bf16 halves of a packed u32 back to fp32 (pure bit placement)
__device__ __forceinline__ float bf_lo_f32(uint32_t p) {
    return __uint_as_float(p << 16);
}
__device__ __forceinline__ float bf_hi_f32(uint32_t p) {
    return __uint_as_float(p & 0xFFFF0000u);
}

// m16n8k16 bf16 MMA, D = A@B + D (fp32 accum)
#define MMA_BF16(d, a, b)                                                     \
    asm volatile("mma.sync.aligned.m16n8k16.row.col.f32.bf16.bf16.f32 "       \
                 "{%0,%1,%2,%3}, {%4,%5,%6,%7}, {%8,%9}, {%0,%1,%2,%3};"      \
                 : "+f"((d)[0]), "+f"((d)[1]), "+f"((d)[2]), "+f"((d)[3])     \
                 : "r"((a)[0]), "r"((a)[1]), "r"((a)[2]), "r"((a)[3]),        \
                   "r"((b)[0]), "r"((b)[1]))

// ---------------------------------------------------------------------------
// Kernel 1: build M = G_comb @ matrix; emit packed-bf16 hi/lo B FRAGMENTS.
// G_comb = I @ G_0 @ ... @ G_31 ; right-multiplying by G_q updates COLUMNS:
//   col_i' = col_i*c + col_j*s ;  col_j' = -col_i*s + col_j*c
// Degenerate i==j (JAX .at sequence leaves G[i,i] = sin): col_i' = col_i*s
// ---------------------------------------------------------------------------
__global__ void build_M_kernel(const float* __restrict__ matrix,
                               const float* __restrict__ thetas,
                               const float* __restrict__ tscale,
                               const int*   __restrict__ pairs) {
    __shared__ float Gs[64][65];
    __shared__ float Mat[64][64];
    __shared__ float Msh[64][64];
    __shared__ float ssin[ROTN], scos[ROTN];
    __shared__ int   sij[ROTN][2];
    const int tid = threadIdx.x;   // 256 threads

    for (int i = tid; i < 64 * 64; i += 256)
        Mat[i >> 6][i & 63] = matrix[i];

    if (tid < ROTN) {                      // sincos once, not per-row
        const float th = thetas[tid] * tscale[0];
        float s, c;
        sincosf(th, &s, &c);
        ssin[tid] = s;
        scos[tid] = c;
        sij[tid][0] = pairs[2 * tid];
        sij[tid][1] = pairs[2 * tid + 1];
    }
    if (tid < 64) {
        #pragma unroll
        for (int k = 0; k < 64; k++) Gs[tid][k] = (tid == k) ? 1.0f : 0.0f;
    }
    __syncthreads();

    if (tid < 64) {
        for (int q = 0; q < ROTN; q++) {
            const int   i = sij[q][0];
            const int   j = sij[q][1];
            const float s = ssin[q];
            const float c = scos[q];
            const float ai = Gs[tid][i];
            const float aj = Gs[tid][j];
            if (i != j) {
                Gs[tid][i] = ai * c + aj * s;
                Gs[tid][j] = -ai * s + aj * c;
            } else {
                Gs[tid][i] = ai * s;
            }
        }
    }
    __syncthreads();

    {
        const int r  = tid >> 2;
        const int qq = tid & 3;
        float gr[64];
        #pragma unroll
        for (int k = 0; k < 64; k++) gr[k] = Gs[r][k];
        #pragma unroll
        for (int n0 = 0; n0 < 16; n0++) {
            const int n = qq * 16 + n0;
            float acc = 0.0f;
            #pragma unroll
            for (int k = 0; k < 64; k++) acc = fmaf(gr[k], Mat[k][n], acc);
            Msh[r][n] = acc;
        }
    }
    __syncthreads();

    // emit fragment-ordered B: hi = bf16(M), lo = bf16(M - hi)
    for (int idx = tid; idx < 4 * 8 * 32; idx += 256) {
        const int frag = idx >> 5;           // kt*8 + j
        const int lane = idx & 31;
        const int kt = frag >> 3, j = frag & 7;
        const int g = lane >> 2, tg = lane & 3;
        const int k0 = kt * 16 + 2 * tg;
        const int n  = 8 * j + g;
        uint4 o;
        {
            const float m0 = Msh[k0][n],     m1 = Msh[k0 + 1][n];
            o.x = pack_bf16x2(m0, m1);
            o.z = pack_bf16x2(m0 - bf_lo_f32(o.x), m1 - bf_hi_f32(o.x));
        }
        {
            const float m0 = Msh[k0 + 8][n], m1 = Msh[k0 + 9][n];
            o.y = pack_bf16x2(m0, m1);
            o.w = pack_bf16x2(m0 - bf_lo_f32(o.y), m1 - bf_hi_f32(o.y));
        }
        g_Bfrag[idx] = o;
    }
}

// ---------------------------------------------------------------------------
// Kernel 2: bf16 m16n8k16 mma.sync GEMM (3-term compensated) + RoPE epilogue.
// R14 design (best so far) at HIGHER OCCUPANCY: __launch_bounds__(128, 3)
// = 3 warps/SMSP for cross-warp latency cover. To fit the 170-reg cap,
// A fragments stay double-buffered (the long-latency LDS path) but B
// fragments are loaded INLINE right before use (transient LDS.128; covered
// cross-warp). R15 showed instruction-count cuts don't help — absolute
// stall cover does.
// A pre-converted to packed bf16x2 hi/lo at stage time, k-pairs permuted
// (0,4,1,5,2,6,3,7) so a fragment's (kp, kp+4) pair is one LDS.64; row
// stride 160 B (conflict-free). Epilogue: RoPE in regs -> STS.32 scatter ->
// coalesced LDS.128 + STG.128.
// ---------------------------------------------------------------------------
#define A_ROW_U32 40                               // 160 B row stride
#define SM_AH    0                                 // 128*160 = 20480 B
#define SM_AL    20480                             // 20480 B
#define SM_BF    40960                             // 16384 B
#define SM_SC    57344                             // 2048 B
#define SMEM_DYN 59392
#define O_STRIDE 68                                // epilogue scatter stride

__global__ __launch_bounds__(128, 3)
void rotary_mma(const float* __restrict__ x,
                const float* __restrict__ invf,
                float* __restrict__ out) {
    extern __shared__ __align__(16) char dsm[];
    uint32_t* Ah  = (uint32_t*)(dsm + SM_AH);
    uint32_t* Al  = (uint32_t*)(dsm + SM_AL);
    uint4*    Bfs = (uint4*)(dsm + SM_BF);
    float2*   sc  = (float2*)(dsm + SM_SC);

    const int tid  = threadIdx.x;
    const int w    = tid >> 5;
    const int lane = tid & 31;
    const int g    = lane >> 2;     // groupID 0..7
    const int tig  = lane & 3;      // threadID_in_group 0..3

    // ---- stage A: fp32 -> packed bf16x2 hi/lo, k-pair permuted ----
    {
        const float4* xg = (const float4*)(x + (size_t)blockIdx.x * 128 * 64);
        #pragma unroll
        for (int i = 0; i < 16; i++) {
            const int idx = i * 128 + tid;        // 16B chunk id, 2048 total
            const int row = idx >> 4;
            const int kq  = idx & 15;
            const float4 v = xg[idx];
            const int kp0 = 2 * kq;               // even kpb in {0,2,4,6}
            const int kt  = kp0 >> 3;
            const int kpb0 = kp0 & 7, kpb1 = kpb0 + 1;
            const int pos0 = (kpb0 < 4) ? 2 * kpb0 : 2 * (kpb0 - 4) + 1;
            const int pos1 = (kpb1 < 4) ? 2 * kpb1 : 2 * (kpb1 - 4) + 1;
            const int base = row * A_ROW_U32 + kt * 8;
            const uint32_t h0 = pack_bf16x2(v.x, v.y);
            const uint32_t h1 = pack_bf16x2(v.z, v.w);
            Ah[base + pos0] = h0;
            Ah[base + pos1] = h1;
            Al[base + pos0] = pack_bf16x2(v.x - bf_lo_f32(h0), v.y - bf_hi_f32(h0));
            Al[base + pos1] = pack_bf16x2(v.z - bf_lo_f32(h1), v.w - bf_hi_f32(h1));
        }
    }

    // ---- stage B fragments: 1024 uint4, 8 per thread ----
    {
        #pragma unroll
        for (int i = 0; i < 8; i++) {
            const int idx = tid + 128 * i;
            Bfs[idx] = g_Bfrag[idx];
        }
    }

    // ---- sincos table: 8 tokens x 32 freqs ----
    {
        #pragma unroll
        for (int e = 0; e < 2; e++) {
            const int idx = tid * 2 + e;          // 256 entries
            const int t = idx >> 5, m = idx & 31;
            const int pos = (blockIdx.x * 8 + t) & (SEQ - 1);
            float sn, cs;
            sincosf((float)pos * invf[m], &sn, &cs);
            sc[idx] = make_float2(sn, cs);
        }
    }
    __syncthreads();

    // ---- mainloop: 4 kt steps; A double-buffered, B inline ----
    float acc[2][8][4];
    #pragma unroll
    for (int mt = 0; mt < 2; mt++)
        #pragma unroll
        for (int j = 0; j < 8; j++)
            #pragma unroll
            for (int q = 0; q < 4; q++) acc[mt][j][q] = 0.0f;

    const int arow = (w * 32 + g) * A_ROW_U32 + 2 * tig;
    const uint4* Bbase = Bfs + lane;

    uint32_t fh[2][2][4], fl[2][2][4];

    // prefetch kt = 0 A fragments
    #pragma unroll
    for (int mt = 0; mt < 2; mt++) {
        const int ro = arow + mt * 16 * A_ROW_U32;
        uint2 t0 = *(const uint2*)(Ah + ro);
        uint2 t1 = *(const uint2*)(Ah + ro + 8 * A_ROW_U32);
        fh[0][mt][0] = t0.x; fh[0][mt][2] = t0.y;
        fh[0][mt][1] = t1.x; fh[0][mt][3] = t1.y;
        t0 = *(const uint2*)(Al + ro);
        t1 = *(const uint2*)(Al + ro + 8 * A_ROW_U32);
        fl[0][mt][0] = t0.x; fl[0][mt][2] = t0.y;
        fl[0][mt][1] = t1.x; fl[0][mt][3] = t1.y;
    }

    #pragma unroll
    for (int kt = 0; kt < 4; kt++) {
        const int cur = kt & 1, nxt = cur ^ 1;
        if (kt < 3) {
            #pragma unroll
            for (int mt = 0; mt < 2; mt++) {
                const int ro = arow + mt * 16 * A_ROW_U32 + (kt + 1) * 8;
                uint2 t0 = *(const uint2*)(Ah + ro);
                uint2 t1 = *(const uint2*)(Ah + ro + 8 * A_ROW_U32);
                fh[nxt][mt][0] = t0.x; fh[nxt][mt][2] = t0.y;
                fh[nxt][mt][1] = t1.x; fh[nxt][mt][3] = t1.y;
                t0 = *(const uint2*)(Al + ro);
                t1 = *(const uint2*)(Al + ro + 8 * A_ROW_U32);
                fl[nxt][mt][0] = t0.x; fl[nxt][mt][2] = t0.y;
                fl[nxt][mt][1] = t1.x; fl[nxt][mt][3] = t1.y;
            }
        }

        #pragma unroll
        for (int j = 0; j < 8; j++) {
            const uint4 bf = Bbase[(kt * 8 + j) * 32];   // inline LDS.128
            uint32_t bh[2] = {bf.x, bf.y};
            uint32_t bl[2] = {bf.z, bf.w};
            #pragma unroll
            for (int mt = 0; mt < 2; mt++) {
                MMA_BF16(acc[mt][j], fh[cur][mt], bh);   // xh @ Mh
                MMA_BF16(acc[mt][j], fl[cur][mt], bh);   // xl @ Mh
                MMA_BF16(acc[mt][j], fh[cur][mt], bl);   // xh @ Ml
            }
        }
    }

    // ---- epilogue: RoPE + *32 in regs, STS.32 scatter (conflict-free),
    //      then coalesced LDS.128 -> STG.128 ----
    __syncthreads();                                     // A/B reads done
    float* Osm = (float*)dsm;                            // reuse as scratch
    #pragma unroll
    for (int mt = 0; mt < 2; mt++) {
        const int tok = 2 * w + mt;
        const int r0 = w * 32 + mt * 16 + g;
        #pragma unroll
        for (int j = 0; j < 8; j++) {
            const int m = 4 * j + tig;
            const float2 scm = sc[tok * 32 + m];         // (sin, cos)
            const float* a = acc[mt][j];
            Osm[r0 * O_STRIDE + m]            = (a[0] * scm.y - a[1] * scm.x) * 32.0f;
            Osm[r0 * O_STRIDE + m + 32]       = (a[0] * scm.x + a[1] * scm.y) * 32.0f;
            Osm[(r0 + 8) * O_STRIDE + m]      = (a[2] * scm.y - a[3] * scm.x) * 32.0f;
            Osm[(r0 + 8) * O_STRIDE + m + 32] = (a[2] * scm.x + a[3] * scm.y) * 32.0f;
        }
    }
    __syncthreads();

    {
        float4* og = (float4*)(out + (size_t)blockIdx.x * 128 * 64);
        #pragma unroll
        for (int i = 0; i < 16; i++) {
            const int idx = i * 128 + tid;        // 16B chunk id, 2048 total
            const int row = idx >> 4;
            const int kq  = idx & 15;
            og[idx] = *(const float4*)(Osm + row * O_STRIDE + kq * 4);
        }
    }
}

// ---------------------------------------------------------------------------
extern "C" void kernel_launch(void* const* d_in, const int* in_sizes, int n_in,
                              void* d_out, int out_size) {
    const float* x      = (const float*)d_in[0];
    const float* matrix = (const float*)d_in[1];
    const float* thetas = (const float*)d_in[2];
    const float* tscale = (const float*)d_in[3];
    const float* invf   = (const float*)d_in[4];
    const int*   pairs  = (const int*)d_in[5];
    float* out = (float*)d_out;

    static bool attr_set = false;
    if (!attr_set) {
        cudaFuncSetAttribute(rotary_mma,
                             cudaFuncAttributeMaxDynamicSharedMemorySize,
                             SMEM_DYN);
        attr_set = true;
    }

    const int nrows  = in_sizes[0] / D;      // 524288
    const int blocks = nrows / 128;          // 4096

    build_M_kernel<<<1, 256>>>(matrix, thetas, tscale, pairs);
    rotary_mma<<<blocks, 128, SMEM_DYN>>>(x, invf, out);
}

// round 17
// speedup vs baseline: 1.4408x; 1.2704x over previous
#include <cuda_runtime.h>
#include <cstdint>

// Problem constants (fixed for rotary_13872744366393):
//   x: (4, 8192, 1024) f32, matrix: (64,64), thetas: (32), tscale: (1),
//   invf: (32), pairs: (32,2) int32. out: (4, 8192, 1024) f32.
#define HEADS 16
#define D     64
#define ROTN  32
#define SEQ   8192

// Pre-built fp16 B fragments for mma.m16n8k16 (single-term):
//   g_Bfrag[(kt*8 + j)*32 + lane] = {b0, b1} packed f16x2
//   b0 = (M[k0][n], M[k0+1][n]), b1 = (M[k0+8][n], M[k0+9][n])
// with k0 = kt*16 + 2*tig, n = 8*j + g  (g = lane>>2, tig = lane&3).
__device__ uint2 g_Bfrag[4 * 8 * 32];     // 8 KB

// pack two fp32 into f16x2 (rn): upper half = hi arg, lower = lo arg
__device__ __forceinline__ uint32_t pack_f16x2(float lo, float hi) {
    uint32_t r;
    asm("cvt.rn.f16x2.f32 %0, %1, %2;" : "=r"(r) : "f"(hi), "f"(lo));
    return r;
}

// m16n8k16 fp16 MMA, D = A@B + D (fp32 accum)
#define MMA_F16(d, a, b)                                                      \
    asm volatile("mma.sync.aligned.m16n8k16.row.col.f32.f16.f16.f32 "         \
                 "{%0,%1,%2,%3}, {%4,%5,%6,%7}, {%8,%9}, {%0,%1,%2,%3};"      \
                 : "+f"((d)[0]), "+f"((d)[1]), "+f"((d)[2]), "+f"((d)[3])     \
                 : "r"((a)[0]), "r"((a)[1]), "r"((a)[2]), "r"((a)[3]),        \
                   "r"((b)[0]), "r"((b)[1]))

// ---------------------------------------------------------------------------
// Kernel 1: build M = G_comb @ matrix; emit fp16 B FRAGMENTS.
// G_comb = I @ G_0 @ ... @ G_31 ; right-multiplying by G_q updates COLUMNS:
//   col_i' = col_i*c + col_j*s ;  col_j' = -col_i*s + col_j*c
// Degenerate i==j (JAX .at sequence leaves G[i,i] = sin): col_i' = col_i*s
// ---------------------------------------------------------------------------
__global__ void build_M_kernel(const float* __restrict__ matrix,
                               const float* __restrict__ thetas,
                               const float* __restrict__ tscale,
                               const int*   __restrict__ pairs) {
    __shared__ float Gs[64][65];
    __shared__ float Mat[64][64];
    __shared__ float Msh[64][64];
    __shared__ float ssin[ROTN], scos[ROTN];
    __shared__ int   sij[ROTN][2];
    const int tid = threadIdx.x;   // 256 threads

    for (int i = tid; i < 64 * 64; i += 256)
        Mat[i >> 6][i & 63] = matrix[i];

    if (tid < ROTN) {                      // sincos once, not per-row
        const float th = thetas[tid] * tscale[0];
        float s, c;
        sincosf(th, &s, &c);
        ssin[tid] = s;
        scos[tid] = c;
        sij[tid][0] = pairs[2 * tid];
        sij[tid][1] = pairs[2 * tid + 1];
    }
    if (tid < 64) {
        #pragma unroll
        for (int k = 0; k < 64; k++) Gs[tid][k] = (tid == k) ? 1.0f : 0.0f;
    }
    __syncthreads();

    if (tid < 64) {
        for (int q = 0; q < ROTN; q++) {
            const int   i = sij[q][0];
            const int   j = sij[q][1];
            const float s = ssin[q];
            const float c = scos[q];
            const float ai = Gs[tid][i];
            const float aj = Gs[tid][j];
            if (i != j) {
                Gs[tid][i] = ai * c + aj * s;
                Gs[tid][j] = -ai * s + aj * c;
            } else {
                Gs[tid][i] = ai * s;
            }
        }
    }
    __syncthreads();

    {
        const int r  = tid >> 2;
        const int qq = tid & 3;
        float gr[64];
        #pragma unroll
        for (int k = 0; k < 64; k++) gr[k] = Gs[r][k];
        #pragma unroll
        for (int n0 = 0; n0 < 16; n0++) {
            const int n = qq * 16 + n0;
            float acc = 0.0f;
            #pragma unroll
            for (int k = 0; k < 64; k++) acc = fmaf(gr[k], Mat[k][n], acc);
            Msh[r][n] = acc;
        }
    }
    __syncthreads();

    // emit fragment-ordered B (single-term fp16)
    for (int idx = tid; idx < 4 * 8 * 32; idx += 256) {
        const int frag = idx >> 5;           // kt*8 + j
        const int lane = idx & 31;
        const int kt = frag >> 3, j = frag & 7;
        const int g = lane >> 2, tg = lane & 3;
        const int k0 = kt * 16 + 2 * tg;
        const int n  = 8 * j + g;
        uint2 o;
        o.x = pack_f16x2(Msh[k0][n],     Msh[k0 + 1][n]);
        o.y = pack_f16x2(Msh[k0 + 8][n], Msh[k0 + 9][n]);
        g_Bfrag[idx] = o;
    }
}

// ---------------------------------------------------------------------------
// Kernel 2: single-term fp16 m16n8k16 mma.sync GEMM + fused RoPE epilogue.
// CTA = 128 threads (4 warps), tile = 128 rows x 64 cols, K = 64 (4 kt).
// Warp w: rows [w*32, w*32+32) = two m16 tiles; 8 n8-tiles cover 64 cols.
// fp16 single term (rel_err ~3e-4 << 1e-3): 64 MMAs per warp (was 192),
// no lo buffers, half the stage conversions.
// A pre-converted to packed f16x2 at stage time, k-pairs permuted
// (0,4,1,5,2,6,3,7) so a fragment's (kp, kp+4) pair is one LDS.64; row
// stride 160 B (conflict-free). B fragments pre-built (LDS.64 inline).
// A double-buffered across kt. __launch_bounds__(128, 4): 16 warps/SM to
// saturate HBM (this kernel should now be DRAM-bound).
// Epilogue: RoPE in regs -> STS.32 scatter -> coalesced LDS.128 + STG.128.
// ---------------------------------------------------------------------------
#define A_ROW_U32 40                               // 160 B row stride
#define SM_AH    0                                 // 128*160 = 20480 B
#define SM_BF    20480                             // 8192 B
#define SM_SC    34816                             // after epilogue scratch
#define SMEM_DYN 36864
#define O_STRIDE 68                                // epilogue scatter stride
                                                   // (128*68*4 = 34816 B)

__global__ __launch_bounds__(128, 4)
void rotary_mma(const float* __restrict__ x,
                const float* __restrict__ invf,
                float* __restrict__ out) {
    extern __shared__ __align__(16) char dsm[];
    uint32_t* Ah  = (uint32_t*)(dsm + SM_AH);
    uint2*    Bfs = (uint2*)(dsm + SM_BF);
    float2*   sc  = (float2*)(dsm + SM_SC);

    const int tid  = threadIdx.x;
    const int w    = tid >> 5;
    const int lane = tid & 31;
    const int g    = lane >> 2;     // groupID 0..7
    const int tig  = lane & 3;      // threadID_in_group 0..3

    // ---- stage A: fp32 -> packed f16x2, k-pair permuted ----
    {
        const float4* xg = (const float4*)(x + (size_t)blockIdx.x * 128 * 64);
        #pragma unroll
        for (int i = 0; i < 16; i++) {
            const int idx = i * 128 + tid;        // 16B chunk id, 2048 total
            const int row = idx >> 4;
            const int kq  = idx & 15;
            const float4 v = xg[idx];
            const int kp0 = 2 * kq;               // even kpb in {0,2,4,6}
            const int kt  = kp0 >> 3;
            const int kpb0 = kp0 & 7, kpb1 = kpb0 + 1;
            const int pos0 = (kpb0 < 4) ? 2 * kpb0 : 2 * (kpb0 - 4) + 1;
            const int pos1 = (kpb1 < 4) ? 2 * kpb1 : 2 * (kpb1 - 4) + 1;
            const int base = row * A_ROW_U32 + kt * 8;
            Ah[base + pos0] = pack_f16x2(v.x, v.y);
            Ah[base + pos1] = pack_f16x2(v.z, v.w);
        }
    }

    // ---- stage B fragments: 1024 uint2, 8 per thread ----
    {
        #pragma unroll
        for (int i = 0; i < 8; i++) {
            const int idx = tid + 128 * i;
            Bfs[idx] = g_Bfrag[idx];
        }
    }

    // ---- sincos table: 8 tokens x 32 freqs ----
    {
        #pragma unroll
        for (int e = 0; e < 2; e++) {
            const int idx = tid * 2 + e;          // 256 entries
            const int t = idx >> 5, m = idx & 31;
            const int pos = (blockIdx.x * 8 + t) & (SEQ - 1);
            float sn, cs;
            sincosf((float)pos * invf[m], &sn, &cs);
            sc[idx] = make_float2(sn, cs);
        }
    }
    __syncthreads();

    // ---- mainloop: 4 kt steps; A double-buffered, B inline LDS.64 ----
    float acc[2][8][4];
    #pragma unroll
    for (int mt = 0; mt < 2; mt++)
        #pragma unroll
        for (int j = 0; j < 8; j++)
            #pragma unroll
            for (int q = 0; q < 4; q++) acc[mt][j][q] = 0.0f;

    const int arow = (w * 32 + g) * A_ROW_U32 + 2 * tig;
    const uint2* Bbase = Bfs + lane;

    uint32_t fh[2][2][4];

    // prefetch kt = 0 A fragments
    #pragma unroll
    for (int mt = 0; mt < 2; mt++) {
        const int ro = arow + mt * 16 * A_ROW_U32;
        const uint2 t0 = *(const uint2*)(Ah + ro);
        const uint2 t1 = *(const uint2*)(Ah + ro + 8 * A_ROW_U32);
        fh[0][mt][0] = t0.x; fh[0][mt][2] = t0.y;
        fh[0][mt][1] = t1.x; fh[0][mt][3] = t1.y;
    }

    #pragma unroll
    for (int kt = 0; kt < 4; kt++) {
        const int cur = kt & 1, nxt = cur ^ 1;
        if (kt < 3) {
            #pragma unroll
            for (int mt = 0; mt < 2; mt++) {
                const int ro = arow + mt * 16 * A_ROW_U32 + (kt + 1) * 8;
                const uint2 t0 = *(const uint2*)(Ah + ro);
                const uint2 t1 = *(const uint2*)(Ah + ro + 8 * A_ROW_U32);
                fh[nxt][mt][0] = t0.x; fh[nxt][mt][2] = t0.y;
                fh[nxt][mt][1] = t1.x; fh[nxt][mt][3] = t1.y;
            }
        }

        #pragma unroll
        for (int j = 0; j < 8; j++) {
            const uint2 bf = Bbase[(kt * 8 + j) * 32];   // inline LDS.64
            uint32_t bb[2] = {bf.x, bf.y};
            #pragma unroll
            for (int mt = 0; mt < 2; mt++) {
                MMA_F16(acc[mt][j], fh[cur][mt], bb);
            }
        }
    }

    // ---- epilogue: RoPE + *32 in regs, STS.32 scatter (conflict-free),
    //      then coalesced LDS.128 -> STG.128 ----
    __syncthreads();                                     // A/B reads done
    float* Osm = (float*)dsm;                            // reuse as scratch
    #pragma unroll
    for (int mt = 0; mt < 2; mt++) {
        const int tok = 2 * w + mt;
        const int r0 = w * 32 + mt * 16 + g;
        #pragma unroll
        for (int j = 0; j < 8; j++) {
            const int m = 4 * j + tig;
            const float2 scm = sc[tok * 32 + m];         // (sin, cos)
            const float* a = acc[mt][j];
            Osm[r0 * O_STRIDE + m]            = (a[0] * scm.y - a[1] * scm.x) * 32.0f;
            Osm[r0 * O_STRIDE + m + 32]       = (a[0] * scm.x + a[1] * scm.y) * 32.0f;
            Osm[(r0 + 8) * O_STRIDE + m]      = (a[2] * scm.y - a[3] * scm.x) * 32.0f;
            Osm[(r0 + 8) * O_STRIDE + m + 32] = (a[2] * scm.x + a[3] * scm.y) * 32.0f;
        }
    }
    __syncthreads();

    {
        float4* og = (float4*)(out + (size_t)blockIdx.x * 128 * 64);
        #pragma unroll
        for (int i = 0; i < 16; i++) {
            const int idx = i * 128 + tid;        // 16B chunk id, 2048 total
            const int row = idx >> 4;
            const int kq  = idx & 15;
            og[idx] = *(const float4*)(Osm + row * O_STRIDE + kq * 4);
        }
    }
}

// ---------------------------------------------------------------------------
extern "C" void kernel_launch(void* const* d_in, const int* in_sizes, int n_in,
                              void* d_out, int out_size) {
    const float* x      = (const float*)d_in[0];
    const float* matrix = (const float*)d_in[1];
    const float* thetas = (const float*)d_in[2];
    const float* tscale = (const float*)d_in[3];
    const float* invf   = (const float*)d_in[4];
    const int*   pairs  = (const int*)d_in[5];
    float* out = (float*)d_out;

    static bool attr_set = false;
    if (!attr_set) {
        cudaFuncSetAttribute(rotary_mma,
                             cudaFuncAttributeMaxDynamicSharedMemorySize,
                             SMEM_DYN);
        attr_set = true;
    }

    const int nrows  = in_sizes[0] / D;      // 524288
    const int blocks = nrows / 128;          // 4096

    build_M_kernel<<<1, 256>>>(matrix, thetas, tscale, pairs);
    rotary_mma<<<blocks, 128, SMEM_DYN>>>(x, invf, out);
}